// round 15
// baseline (speedup 1.0000x reference)
#include <cuda_runtime.h>
#include <cuda_bf16.h>
#include <cfloat>
#include <cstdint>

#define NN 100000
#define CC 200
#define EE 400000
#define GG 512
#define HH 4
#define DD 50
#define SCAN_B 1024
#define SCAN_NB ((NN + SCAN_B - 1) / SCAN_B)
#define KP 104                 // padded K in u32-pair units (208 bf16)
#define NTILES 26
#define KTILES 13
#define ROWTILES (NN / 16)     // 6250
#define NTQ_MAX 7
#define SMEM_Q (NTQ_MAX * KTILES * 32 * 16)   // 46592 bytes

// ---------------- scratch ----------------------------------------------------
__device__ __align__(16) float g_xh[(size_t)NN * CC];
__device__ __align__(16) float g_asrc[NN * HH];
__device__ __align__(16) float g_adst[NN * HH];
__device__ float g_gsum[GG], g_gsq[GG], g_gcnt[GG];
__device__ float g_srel[NN], g_sbase[NN], g_es[NN];
__device__ unsigned g_gmu[GG];
__device__ float g_gz[GG];
// packed bf16 A image: u64 = hi_pair | lo_pair<<32
__device__ __align__(16) unsigned long long g_Apk[(size_t)NN * KP];
// fragment-packed B image: uint4 = {bh0, bh1, bl0, bl1}
__device__ __align__(16) uint4 g_Bpk[NTILES * KTILES * 32];
// CSR
__device__ int g_cnt[NN];
__device__ int g_base[NN];
__device__ int g_cursor[NN];
__device__ int g_csrc[EE];
__device__ int g_bsum[SCAN_NB];

// ---------------- helpers ----------------------------------------------------
__device__ __forceinline__ unsigned fkey(float f) {
    unsigned b = __float_as_uint(f);
    return b ^ ((unsigned)((int)b >> 31) | 0x80000000u);
}
__device__ __forceinline__ float funkey(unsigned u) {
    unsigned b = (u & 0x80000000u) ? (u ^ 0x80000000u) : ~u;
    return __uint_as_float(b);
}
__device__ __forceinline__ float warpSum(float v) {
#pragma unroll
    for (int o = 16; o; o >>= 1) v += __shfl_xor_sync(0xffffffffu, v, o);
    return v;
}
__device__ __forceinline__ float warpMax(float v) {
#pragma unroll
    for (int o = 16; o; o >>= 1) v = fmaxf(v, __shfl_xor_sync(0xffffffffu, v, o));
    return v;
}
__device__ __forceinline__ float lrelu(float a) { return a > 0.f ? a : 0.2f * a; }
__device__ __forceinline__ void red_add_v4(float* addr, float a, float b, float c, float d) {
    asm volatile("red.global.add.v4.f32 [%0], {%1, %2, %3, %4};"
                 :: "l"(addr), "f"(a), "f"(b), "f"(c), "f"(d) : "memory");
}
__device__ __forceinline__ unsigned short f2bf(float v) {
    __nv_bfloat16 b = __float2bfloat16(v);
    return *reinterpret_cast<unsigned short*>(&b);
}
__device__ __forceinline__ float bf2f(unsigned short u) {
    __nv_bfloat16 b;
    *reinterpret_cast<unsigned short*>(&b) = u;
    return __bfloat162float(b);
}
__device__ __forceinline__ void mma16816(float* c, const uint32_t* a,
                                         uint32_t b0, uint32_t b1) {
    asm volatile(
        "mma.sync.aligned.m16n8k16.row.col.f32.bf16.bf16.f32 "
        "{%0,%1,%2,%3}, {%4,%5,%6,%7}, {%8,%9}, {%0,%1,%2,%3};"
        : "+f"(c[0]), "+f"(c[1]), "+f"(c[2]), "+f"(c[3])
        : "r"(a[0]), "r"(a[1]), "r"(a[2]), "r"(a[3]), "r"(b0), "r"(b1));
}

// ---------------- kernels ----------------------------------------------------

// init + B fragment pack + zero attention logit accumulators
__global__ void k_init(float* __restrict__ outg, const float* __restrict__ W) {
    int i = blockIdx.x * blockDim.x + threadIdx.x;
    if (i < NN) {
        g_cnt[i] = 0;
        float4 z = make_float4(0.f, 0.f, 0.f, 0.f);
        *(float4*)&g_asrc[i * 4] = z;
        *(float4*)&g_adst[i * 4] = z;
    }
    if (i < GG * (CC / 4))
        *(float4*)&outg[(size_t)i * 4] = make_float4(0.f, 0.f, 0.f, 0.f);
    if (i < GG) {
        g_gsum[i] = 0.f; g_gsq[i] = 0.f; g_gcnt[i] = 0.f;
        g_gmu[i] = 0u; g_gz[i] = 0.f;
    }
    if (i < NTILES * KTILES * 32) {
        int lane = i & 31;
        int kt = (i >> 5) % KTILES;
        int nt = (i >> 5) / KTILES;
        int n = nt * 8 + (lane >> 2);
        int k0 = kt * 16 + (lane & 3) * 2;
        float w00 = 0.f, w01 = 0.f, w10 = 0.f, w11 = 0.f;
        if (n < CC) {
            if (k0 < CC) w00 = W[k0 * CC + n];
            if (k0 + 1 < CC) w01 = W[(k0 + 1) * CC + n];
            if (k0 + 8 < CC) w10 = W[(k0 + 8) * CC + n];
            if (k0 + 9 < CC) w11 = W[(k0 + 9) * CC + n];
        }
        unsigned short h00 = f2bf(w00), h01 = f2bf(w01), h10 = f2bf(w10), h11 = f2bf(w11);
        unsigned short l00 = f2bf(w00 - bf2f(h00)), l01 = f2bf(w01 - bf2f(h01));
        unsigned short l10 = f2bf(w10 - bf2f(h10)), l11 = f2bf(w11 - bf2f(h11));
        uint4 v;
        v.x = (uint32_t)h00 | ((uint32_t)h01 << 16);
        v.y = (uint32_t)h10 | ((uint32_t)h11 << 16);
        v.z = (uint32_t)l00 | ((uint32_t)l01 << 16);
        v.w = (uint32_t)l10 | ((uint32_t)l11 << 16);
        g_Bpk[i] = v;
    }
}

// LN stats (warp per node) + fused edge in-degree count
__global__ void k_ln_stats(const float* __restrict__ x,
                           const int* __restrict__ batch,
                           const int* __restrict__ ei) {
    int gtid = blockIdx.x * blockDim.x + threadIdx.x;
    if (gtid < EE) atomicAdd(&g_cnt[ei[EE + gtid]], 1);

    int gw = gtid >> 5;
    int lane = threadIdx.x & 31;
    if (gw >= NN) return;
    const float* row = &x[(size_t)gw * CC];
    float s = 0.f, s2 = 0.f;
#pragma unroll
    for (int t = 0; t < 2; t++) {
        int c4 = lane + t * 32;
        if (c4 < CC / 4) {
            float4 v = *(const float4*)&row[c4 * 4];
            s += v.x + v.y + v.z + v.w;
            s2 += v.x * v.x + v.y * v.y + v.z * v.z + v.w * v.w;
        }
    }
    s = warpSum(s); s2 = warpSum(s2);
    if (lane == 0) {
        int b = batch[gw];
        atomicAdd(&g_gsum[b], s);
        atomicAdd(&g_gsq[b], s2);
        atomicAdd(&g_gcnt[b], 1.f);
    }
}

// A prep (warp per row): LN+ELU -> packed bf16 hi|lo u64
__global__ void k_aprep(const float* __restrict__ x, const int* __restrict__ batch,
                        const float* __restrict__ lnw, const float* __restrict__ lnb) {
    int gw = (blockIdx.x * blockDim.x + threadIdx.x) >> 5;
    int lane = threadIdx.x & 31;
    if (gw >= NN) return;
    float mean = 0.f, inv = 0.f;
    if (lane == 0) {
        int b = batch[gw];
        float denom = g_gcnt[b] * (float)CC;
        mean = g_gsum[b] / denom;
        float var = g_gsq[b] / denom - mean * mean;
        inv = rsqrtf(var + 1e-5f);
    }
    mean = __shfl_sync(0xffffffffu, mean, 0);
    inv = __shfl_sync(0xffffffffu, inv, 0);
    const float* xr = &x[(size_t)gw * CC];
#pragma unroll
    for (int t = 0; t < 4; t++) {
        int p = lane + t * 32;
        if (p >= KP) break;
        float v0 = 0.f, v1 = 0.f;
        int k = p * 2;
        if (k < CC) {
            float2 xv = *(const float2*)&xr[k];
            v0 = (xv.x - mean) * inv * __ldg(&lnw[k]) + __ldg(&lnb[k]);
            v1 = (xv.y - mean) * inv * __ldg(&lnw[k + 1]) + __ldg(&lnb[k + 1]);
            v0 = v0 > 0.f ? v0 : (__expf(v0) - 1.f);
            v1 = v1 > 0.f ? v1 : (__expf(v1) - 1.f);
        }
        unsigned short h0 = f2bf(v0), h1 = f2bf(v1);
        unsigned short l0 = f2bf(v0 - bf2f(h0)), l1 = f2bf(v1 - bf2f(h1));
        g_Apk[(size_t)gw * KP + p] =
            (unsigned long long)((uint32_t)h0 | ((uint32_t)h1 << 16)) |
            ((unsigned long long)((uint32_t)l0 | ((uint32_t)l1 << 16)) << 32);
    }
}

// ---- HMMA GEMM: quarter n-tiling (7/6 nt per CTA) for 3 CTAs/SM ----
__global__ void __launch_bounds__(256, 3) k_gemm_mma(const float* __restrict__ att_s,
                                                     const float* __restrict__ att_d) {
    extern __shared__ uint4 sB[];          // <= 2912 uint4 = 46.6 KB
    const int tid = threadIdx.x;
    const int quarter = blockIdx.x & 3;
    const int tile = (blockIdx.x >> 2) * 8 + (tid >> 5);
    const int lane = tid & 31;

    // quarter -> base n-tile and count: {0:7, 7:6, 13:7, 20:6}
    const int ntbase = (quarter == 0) ? 0 : (quarter == 1) ? 7 : (quarter == 2) ? 13 : 20;
    const int ntcnt  = (quarter & 1) ? 6 : 7;
    const int bq = ntcnt * KTILES * 32;

    for (int i = tid; i < bq; i += 256)
        sB[i] = g_Bpk[ntbase * KTILES * 32 + i];
    __syncthreads();

    if (tile >= ROWTILES) return;
    const int r = tile * 16 + (lane >> 2);
    const int q = lane & 3;

    float acc[NTQ_MAX][4];
#pragma unroll
    for (int nt = 0; nt < NTQ_MAX; nt++)
#pragma unroll
        for (int t = 0; t < 4; t++) acc[nt][t] = 0.f;

    const unsigned long long* A0 = &g_Apk[(size_t)r * KP + q];
    const unsigned long long* A1 = &g_Apk[(size_t)(r + 8) * KP + q];
    unsigned long long v0 = A0[0], v1 = A1[0], v2 = A0[4], v3 = A1[4];

#pragma unroll
    for (int kt = 0; kt < KTILES; kt++) {
        uint32_t ahi[4] = {(uint32_t)v0, (uint32_t)v1, (uint32_t)v2, (uint32_t)v3};
        uint32_t alo[4] = {(uint32_t)(v0 >> 32), (uint32_t)(v1 >> 32),
                           (uint32_t)(v2 >> 32), (uint32_t)(v3 >> 32)};
        if (kt + 1 < KTILES) {
            int o = (kt + 1) * 8;
            v0 = A0[o]; v1 = A1[o]; v2 = A0[o + 4]; v3 = A1[o + 4];
        }
#pragma unroll
        for (int nt = 0; nt < NTQ_MAX; nt++) {
            if (nt >= ntcnt) break;
            uint4 b = sB[(nt * KTILES + kt) * 32 + lane];
            mma16816(acc[nt], ahi, b.x, b.y);
            mma16816(acc[nt], ahi, b.z, b.w);
            mma16816(acc[nt], alo, b.x, b.y);
        }
    }

    // epilogue: store xh + partial attention head dots (this quarter's columns)
    float s0A = 0.f, s1A = 0.f, s2A = 0.f, s3A = 0.f;
    float d0A = 0.f, d1A = 0.f, d2A = 0.f, d3A = 0.f;
    float s0B = 0.f, s1B = 0.f, s2B = 0.f, s3B = 0.f;
    float d0B = 0.f, d1B = 0.f, d2B = 0.f, d3B = 0.f;

#pragma unroll
    for (int nt = 0; nt < NTQ_MAX; nt++) {
        if (nt >= ntcnt) break;
        int n0 = (ntbase + nt) * 8;
        if (n0 >= CC) break;
        int col = n0 + q * 2;
        *(float2*)&g_xh[(size_t)r * CC + col] = make_float2(acc[nt][0], acc[nt][1]);
        *(float2*)&g_xh[(size_t)(r + 8) * CC + col] = make_float2(acc[nt][2], acc[nt][3]);

        float2 as = __ldg((const float2*)&att_s[col]);
        float2 adv = __ldg((const float2*)&att_d[col]);
        float psA = acc[nt][0] * as.x + acc[nt][1] * as.y;
        float pdA = acc[nt][0] * adv.x + acc[nt][1] * adv.y;
        float psB = acc[nt][2] * as.x + acc[nt][3] * as.y;
        float pdB = acc[nt][2] * adv.x + acc[nt][3] * adv.y;
        int h = col / DD;   // pairs never straddle a head boundary (50 even)
        if (h == 0)      { s0A += psA; d0A += pdA; s0B += psB; d0B += pdB; }
        else if (h == 1) { s1A += psA; d1A += pdA; s1B += psB; d1B += pdB; }
        else if (h == 2) { s2A += psA; d2A += pdA; s2B += psB; d2B += pdB; }
        else             { s3A += psA; d3A += pdA; s3B += psB; d3B += pdB; }
    }
#pragma unroll
    for (int o = 1; o <= 2; o <<= 1) {
        s0A += __shfl_xor_sync(0xffffffffu, s0A, o);
        s1A += __shfl_xor_sync(0xffffffffu, s1A, o);
        s2A += __shfl_xor_sync(0xffffffffu, s2A, o);
        s3A += __shfl_xor_sync(0xffffffffu, s3A, o);
        d0A += __shfl_xor_sync(0xffffffffu, d0A, o);
        d1A += __shfl_xor_sync(0xffffffffu, d1A, o);
        d2A += __shfl_xor_sync(0xffffffffu, d2A, o);
        d3A += __shfl_xor_sync(0xffffffffu, d3A, o);
        s0B += __shfl_xor_sync(0xffffffffu, s0B, o);
        s1B += __shfl_xor_sync(0xffffffffu, s1B, o);
        s2B += __shfl_xor_sync(0xffffffffu, s2B, o);
        s3B += __shfl_xor_sync(0xffffffffu, s3B, o);
        d0B += __shfl_xor_sync(0xffffffffu, d0B, o);
        d1B += __shfl_xor_sync(0xffffffffu, d1B, o);
        d2B += __shfl_xor_sync(0xffffffffu, d2B, o);
        d3B += __shfl_xor_sync(0xffffffffu, d3B, o);
    }
    if (q == 0) {
        red_add_v4(&g_asrc[r * 4], s0A, s1A, s2A, s3A);
        red_add_v4(&g_adst[r * 4], d0A, d1A, d2A, d3A);
        red_add_v4(&g_asrc[(r + 8) * 4], s0B, s1B, s2B, s3B);
        red_add_v4(&g_adst[(r + 8) * 4], d0B, d1B, d2B, d3B);
    }
}

// ---- CSR build ----
__global__ void k_scan_block() {
    __shared__ int sm[SCAN_B];
    int i = blockIdx.x * SCAN_B + threadIdx.x;
    int v = (i < NN) ? g_cnt[i] : 0;
    sm[threadIdx.x] = v;
    __syncthreads();
    for (int o = 1; o < SCAN_B; o <<= 1) {
        int t = (threadIdx.x >= o) ? sm[threadIdx.x - o] : 0;
        __syncthreads();
        sm[threadIdx.x] += t;
        __syncthreads();
    }
    if (i < NN) g_base[i] = sm[threadIdx.x] - v;
    if (threadIdx.x == SCAN_B - 1) g_bsum[blockIdx.x] = sm[threadIdx.x];
}

// per-block prefix of g_bsum computed in-kernel
__global__ void k_scan_add() {
    __shared__ float s_off;
    if (threadIdx.x < 32) {
        int bid = blockIdx.x;
        int off = 0;
        for (int j = (int)threadIdx.x; j < bid; j += 32) off += g_bsum[j];
#pragma unroll
        for (int o = 16; o; o >>= 1) off += __shfl_xor_sync(0xffffffffu, off, o);
        if (threadIdx.x == 0) s_off = __int_as_float(off);
    }
    __syncthreads();
    int off = __float_as_int(s_off);
    int i = blockIdx.x * SCAN_B + threadIdx.x;
    if (i >= NN) return;
    int v = g_base[i] + off;
    g_base[i] = v;
    g_cursor[i] = v;
}

__global__ void k_fill(const int* __restrict__ ei) {
    int i = blockIdx.x * blockDim.x + threadIdx.x;
    if (i >= EE) return;
    int dst = ei[EE + i];
    int pos = atomicAdd(&g_cursor[dst], 1);
    g_csrc[pos] = ei[i];
}

// ---- GAT softmax + aggregation + SAG score projections (float4 gather) ----
__global__ void __launch_bounds__(256) k_gat(float* __restrict__ out,
                                             const float* __restrict__ bias,
                                             const float* __restrict__ w_rel,
                                             const float* __restrict__ w_root,
                                             const float* __restrict__ b_rel) {
    __shared__ float s_e[8][32][4];
    __shared__ int s_src[8][32];
    __shared__ float s_zz[8][4], s_ee[8][4];
    int w = threadIdx.x >> 5;
    int lane = threadIdx.x & 31;
    int n = blockIdx.x * 8 + w;
    if (n >= NN) return;
    int base = g_base[n];
    int deg = g_cnt[n];
    const bool two = lane < 18;

    const int c0 = lane * 4;
    const int c1 = (lane + 32) * 4;
    const int h00 = c0 / DD, h01 = (c0 + 1) / DD, h02 = (c0 + 2) / DD, h03 = (c0 + 3) / DD;
    const int h10 = two ? c1 / DD : 3, h11 = two ? (c1 + 1) / DD : 3;
    const int h12 = two ? (c1 + 2) / DD : 3, h13 = two ? (c1 + 3) / DD : 3;

    float4 ad = *(const float4*)&g_adst[n * 4];
    float4 asn = *(const float4*)&g_asrc[n * 4];
    float sf0 = lrelu(asn.x + ad.x), sf1 = lrelu(asn.y + ad.y);
    float sf2 = lrelu(asn.z + ad.z), sf3 = lrelu(asn.w + ad.w);

    float m0 = sf0, m1 = sf1, m2 = sf2, m3 = sf3;
    for (int j = lane; j < deg; j += 32) {
        int src = g_csrc[base + j];
        float4 as = *(const float4*)&g_asrc[src * 4];
        m0 = fmaxf(m0, lrelu(as.x + ad.x));
        m1 = fmaxf(m1, lrelu(as.y + ad.y));
        m2 = fmaxf(m2, lrelu(as.z + ad.z));
        m3 = fmaxf(m3, lrelu(as.w + ad.w));
    }
    m0 = warpMax(m0); m1 = warpMax(m1); m2 = warpMax(m2); m3 = warpMax(m3);

    float4 acc0 = make_float4(0.f, 0.f, 0.f, 0.f);
    float4 acc1 = make_float4(0.f, 0.f, 0.f, 0.f);
    float z0 = 0.f, z1 = 0.f, z2 = 0.f, z3 = 0.f;

    for (int cbase = 0; cbase < deg; cbase += 32) {
        int j = cbase + lane;
        int cn = min(32, deg - cbase);
        if (j < deg) {
            int src = g_csrc[base + j];
            s_src[w][lane] = src;
            float4 as = *(const float4*)&g_asrc[src * 4];
            float e0 = __expf(lrelu(as.x + ad.x) - m0);
            float e1 = __expf(lrelu(as.y + ad.y) - m1);
            float e2 = __expf(lrelu(as.z + ad.z) - m2);
            float e3 = __expf(lrelu(as.w + ad.w) - m3);
            s_e[w][lane][0] = e0; s_e[w][lane][1] = e1;
            s_e[w][lane][2] = e2; s_e[w][lane][3] = e3;
            z0 += e0; z1 += e1; z2 += e2; z3 += e3;
        }
        __syncwarp();
        for (int jj = 0; jj < cn; jj++) {
            int src = s_src[w][jj];
            const float4* xr = (const float4*)&g_xh[(size_t)src * CC];
            float4 xv0 = xr[lane];
            acc0.x += xv0.x * s_e[w][jj][h00];
            acc0.y += xv0.y * s_e[w][jj][h01];
            acc0.z += xv0.z * s_e[w][jj][h02];
            acc0.w += xv0.w * s_e[w][jj][h03];
            if (two) {
                float4 xv1 = xr[lane + 32];
                acc1.x += xv1.x * s_e[w][jj][h10];
                acc1.y += xv1.y * s_e[w][jj][h11];
                acc1.z += xv1.z * s_e[w][jj][h12];
                acc1.w += xv1.w * s_e[w][jj][h13];
            }
        }
        __syncwarp();
    }
    z0 = warpSum(z0); z1 = warpSum(z1); z2 = warpSum(z2); z3 = warpSum(z3);

    float es0 = __expf(sf0 - m0), es1 = __expf(sf1 - m1);
    float es2 = __expf(sf2 - m2), es3 = __expf(sf3 - m3);
    z0 += es0 + 1e-16f; z1 += es1 + 1e-16f;
    z2 += es2 + 1e-16f; z3 += es3 + 1e-16f;
    if (lane == 0) {
        s_zz[w][0] = z0; s_zz[w][1] = z1; s_zz[w][2] = z2; s_zz[w][3] = z3;
        s_ee[w][0] = es0; s_ee[w][1] = es1; s_ee[w][2] = es2; s_ee[w][3] = es3;
    }
    __syncwarp();

    const float4* xn4 = (const float4*)&g_xh[(size_t)n * CC];
    float4* orow4 = (float4*)&out[(size_t)n * CC];
    float sr = 0.f, sb = 0.f;
    {
        float4 xv = xn4[lane];
        float4 bv = __ldg((const float4*)&bias[c0]);
        float4 wr = __ldg((const float4*)&w_rel[c0]);
        float4 wo = __ldg((const float4*)&w_root[c0]);
        float4 v;
        v.x = (acc0.x + xv.x * s_ee[w][h00]) / s_zz[w][h00] + bv.x;
        v.y = (acc0.y + xv.y * s_ee[w][h01]) / s_zz[w][h01] + bv.y;
        v.z = (acc0.z + xv.z * s_ee[w][h02]) / s_zz[w][h02] + bv.z;
        v.w = (acc0.w + xv.w * s_ee[w][h03]) / s_zz[w][h03] + bv.w;
        orow4[lane] = v;
        sr += v.x * wr.x + v.y * wr.y + v.z * wr.z + v.w * wr.w;
        sb += v.x * wo.x + v.y * wo.y + v.z * wo.z + v.w * wo.w;
    }
    if (two) {
        float4 xv = xn4[lane + 32];
        float4 bv = __ldg((const float4*)&bias[c1]);
        float4 wr = __ldg((const float4*)&w_rel[c1]);
        float4 wo = __ldg((const float4*)&w_root[c1]);
        float4 v;
        v.x = (acc1.x + xv.x * s_ee[w][h10]) / s_zz[w][h10] + bv.x;
        v.y = (acc1.y + xv.y * s_ee[w][h11]) / s_zz[w][h11] + bv.y;
        v.z = (acc1.z + xv.z * s_ee[w][h12]) / s_zz[w][h12] + bv.z;
        v.w = (acc1.w + xv.w * s_ee[w][h13]) / s_zz[w][h13] + bv.w;
        orow4[lane + 32] = v;
        sr += v.x * wr.x + v.y * wr.y + v.z * wr.z + v.w * wr.w;
        sb += v.x * wo.x + v.y * wo.y + v.z * wo.z + v.w * wo.w;
    }
    sr = warpSum(sr); sb = warpSum(sb);
    if (lane == 0) {
        g_srel[n] = sr;
        g_sbase[n] = sb + __ldg(&b_rel[0]);
    }
}

__global__ void k_score_agg(const int* __restrict__ batch) {
    int i = blockIdx.x * blockDim.x + threadIdx.x;
    if (i >= NN) return;
    int base = g_base[i], deg = g_cnt[i];
    float s = 0.f;
    for (int j = 0; j < deg; j++) s += g_srel[g_csrc[base + j]];
    s += g_sbase[i];
    g_sbase[i] = s;
    atomicMax(&g_gmu[batch[i]], fkey(s));
}

__global__ void k_score_exp(const int* __restrict__ batch) {
    int i = blockIdx.x * blockDim.x + threadIdx.x;
    if (i >= NN) return;
    int b = batch[i];
    float es = expf(g_sbase[i] - funkey(g_gmu[b]));
    g_es[i] = es;
    atomicAdd(&g_gz[b], es);
}

// finalize: warp per 16-node run; inline scale; per-graph register accumulation
__global__ void k_finalize(float* __restrict__ out, float* __restrict__ outg,
                           const int* __restrict__ batch) {
    int gw = (blockIdx.x * blockDim.x + threadIdx.x) >> 5;
    int lane = threadIdx.x & 31;
    if (gw >= NN / 16) return;
    const bool two = lane < 18;
    int n0 = gw * 16;
    float4 a0 = make_float4(0.f, 0.f, 0.f, 0.f);
    float4 a1 = make_float4(0.f, 0.f, 0.f, 0.f);
    int curb = batch[n0];
    for (int j = 0; j < 16; j++) {
        int n = n0 + j;
        int b = batch[n];
        if (b != curb) {
            red_add_v4(&outg[(size_t)curb * CC + lane * 4], a0.x, a0.y, a0.z, a0.w);
            if (two)
                red_add_v4(&outg[(size_t)curb * CC + (lane + 32) * 4], a1.x, a1.y, a1.z, a1.w);
            a0 = make_float4(0.f, 0.f, 0.f, 0.f);
            a1 = make_float4(0.f, 0.f, 0.f, 0.f);
            curb = b;
        }
        float sc = g_es[n] / g_gz[b];
        float4* orow = (float4*)&out[(size_t)n * CC];
        float4 v = orow[lane];
        v.x *= sc; v.y *= sc; v.z *= sc; v.w *= sc;
        orow[lane] = v;
        a0.x += v.x; a0.y += v.y; a0.z += v.z; a0.w += v.w;
        if (two) {
            float4 v1 = orow[lane + 32];
            v1.x *= sc; v1.y *= sc; v1.z *= sc; v1.w *= sc;
            orow[lane + 32] = v1;
            a1.x += v1.x; a1.y += v1.y; a1.z += v1.z; a1.w += v1.w;
        }
    }
    red_add_v4(&outg[(size_t)curb * CC + lane * 4], a0.x, a0.y, a0.z, a0.w);
    if (two)
        red_add_v4(&outg[(size_t)curb * CC + (lane + 32) * 4], a1.x, a1.y, a1.z, a1.w);
}

// ---------------- launch ----------------------------------------------------
extern "C" void kernel_launch(void* const* d_in, const int* in_sizes, int n_in,
                              void* d_out, int out_size) {
    const float* x = (const float*)d_in[0];
    const int* ei = (const int*)d_in[1];
    const int* batch = (const int*)d_in[2];
    const float* ln_w = (const float*)d_in[3];
    const float* ln_b = (const float*)d_in[4];
    const float* W_gat = (const float*)d_in[5];
    const float* att_s = (const float*)d_in[6];
    const float* att_d = (const float*)d_in[7];
    const float* bias = (const float*)d_in[8];
    const float* w_rel = (const float*)d_in[9];
    const float* b_rel = (const float*)d_in[10];
    const float* w_root = (const float*)d_in[11];

    float* out = (float*)d_out;
    float* outg = out + (size_t)NN * CC;

    const int T = 256;
    const int warpNodeBlocks = (NN + 7) / 8;
    const int nodeBlocks = (NN + T - 1) / T;
    const int edgeBlocks = (EE + T - 1) / T;
    (void)in_sizes; (void)n_in; (void)out_size;

    cudaFuncSetAttribute(k_gemm_mma, cudaFuncAttributeMaxDynamicSharedMemorySize,
                         SMEM_Q);

    k_init<<<nodeBlocks, T>>>(outg, W_gat);
    k_ln_stats<<<warpNodeBlocks, T>>>(x, batch, ei);   // + edge count
    k_aprep<<<warpNodeBlocks, T>>>(x, batch, ln_w, ln_b);

    // 4th launch -> profiled; quarters interleave so A tiles stay L2-hot
    k_gemm_mma<<<((ROWTILES + 7) / 8) * 4, 256, SMEM_Q>>>(att_s, att_d);

    k_scan_block<<<SCAN_NB, SCAN_B>>>();
    k_scan_add<<<SCAN_NB, SCAN_B>>>();
    k_fill<<<edgeBlocks, T>>>(ei);

    k_gat<<<warpNodeBlocks, T>>>(out, bias, w_rel, w_root, b_rel);

    k_score_agg<<<nodeBlocks, T>>>(batch);
    k_score_exp<<<nodeBlocks, T>>>(batch);
    k_finalize<<<(NN / 16 + 7) / 8, T>>>(out, outg, batch);
}

// round 16
// speedup vs baseline: 1.0519x; 1.0519x over previous
#include <cuda_runtime.h>
#include <cuda_bf16.h>
#include <cfloat>
#include <cstdint>

#define NN 100000
#define CC 200
#define EE 400000
#define GG 512
#define HH 4
#define DD 50
#define SCAN_B 1024
#define SCAN_NB ((NN + SCAN_B - 1) / SCAN_B)
#define KP 104                 // padded K in u32-pair units (208 bf16)
#define NTILES 26
#define KTILES 13
#define ROWTILES (NN / 16)     // 6250
#define BHALF (13 * KTILES * 32)           // 5408 uint4 per half
#define SMEM_B (BHALF * 16)                // 86528 bytes

// ---------------- scratch ----------------------------------------------------
__device__ __align__(16) float g_xh[(size_t)NN * CC];
__device__ __align__(16) float g_asrc[NN * HH];
__device__ __align__(16) float g_adst[NN * HH];
__device__ float g_gsum[GG], g_gsq[GG], g_gcnt[GG];
__device__ float g_srel[NN], g_sbase[NN], g_es[NN];
__device__ unsigned g_gmu[GG];
__device__ float g_gz[GG];
// packed bf16 A image: u64 = hi_pair | lo_pair<<32
__device__ __align__(16) unsigned long long g_Apk[(size_t)NN * KP];
// fragment-packed B image: uint4 = {bh0, bh1, bl0, bl1}
__device__ __align__(16) uint4 g_Bpk[NTILES * KTILES * 32];
// CSR
__device__ int g_cnt[NN];
__device__ int g_base[NN];
__device__ int g_cursor[NN];
__device__ int g_csrc[EE];
__device__ int g_bsum[SCAN_NB];

// ---------------- helpers ----------------------------------------------------
__device__ __forceinline__ unsigned fkey(float f) {
    unsigned b = __float_as_uint(f);
    return b ^ ((unsigned)((int)b >> 31) | 0x80000000u);
}
__device__ __forceinline__ float funkey(unsigned u) {
    unsigned b = (u & 0x80000000u) ? (u ^ 0x80000000u) : ~u;
    return __uint_as_float(b);
}
__device__ __forceinline__ float warpSum(float v) {
#pragma unroll
    for (int o = 16; o; o >>= 1) v += __shfl_xor_sync(0xffffffffu, v, o);
    return v;
}
__device__ __forceinline__ float warpMax(float v) {
#pragma unroll
    for (int o = 16; o; o >>= 1) v = fmaxf(v, __shfl_xor_sync(0xffffffffu, v, o));
    return v;
}
__device__ __forceinline__ float lrelu(float a) { return a > 0.f ? a : 0.2f * a; }
__device__ __forceinline__ void red_add_v4(float* addr, float a, float b, float c, float d) {
    asm volatile("red.global.add.v4.f32 [%0], {%1, %2, %3, %4};"
                 :: "l"(addr), "f"(a), "f"(b), "f"(c), "f"(d) : "memory");
}
__device__ __forceinline__ unsigned short f2bf(float v) {
    __nv_bfloat16 b = __float2bfloat16(v);
    return *reinterpret_cast<unsigned short*>(&b);
}
__device__ __forceinline__ float bf2f(unsigned short u) {
    __nv_bfloat16 b;
    *reinterpret_cast<unsigned short*>(&b) = u;
    return __bfloat162float(b);
}
__device__ __forceinline__ void mma16816(float* c, const uint32_t* a,
                                         uint32_t b0, uint32_t b1) {
    asm volatile(
        "mma.sync.aligned.m16n8k16.row.col.f32.bf16.bf16.f32 "
        "{%0,%1,%2,%3}, {%4,%5,%6,%7}, {%8,%9}, {%0,%1,%2,%3};"
        : "+f"(c[0]), "+f"(c[1]), "+f"(c[2]), "+f"(c[3])
        : "r"(a[0]), "r"(a[1]), "r"(a[2]), "r"(a[3]), "r"(b0), "r"(b1));
}

// ---------------- kernels ----------------------------------------------------

// init + B fragment pack + zero attention logit accumulators
__global__ void k_init(float* __restrict__ outg, const float* __restrict__ W) {
    int i = blockIdx.x * blockDim.x + threadIdx.x;
    if (i < NN) {
        g_cnt[i] = 0;
        float4 z = make_float4(0.f, 0.f, 0.f, 0.f);
        *(float4*)&g_asrc[i * 4] = z;
        *(float4*)&g_adst[i * 4] = z;
    }
    if (i < GG * (CC / 4))
        *(float4*)&outg[(size_t)i * 4] = make_float4(0.f, 0.f, 0.f, 0.f);
    if (i < GG) {
        g_gsum[i] = 0.f; g_gsq[i] = 0.f; g_gcnt[i] = 0.f;
        g_gmu[i] = 0u; g_gz[i] = 0.f;
    }
    if (i < NTILES * KTILES * 32) {
        int lane = i & 31;
        int kt = (i >> 5) % KTILES;
        int nt = (i >> 5) / KTILES;
        int n = nt * 8 + (lane >> 2);
        int k0 = kt * 16 + (lane & 3) * 2;
        float w00 = 0.f, w01 = 0.f, w10 = 0.f, w11 = 0.f;
        if (n < CC) {
            if (k0 < CC) w00 = W[k0 * CC + n];
            if (k0 + 1 < CC) w01 = W[(k0 + 1) * CC + n];
            if (k0 + 8 < CC) w10 = W[(k0 + 8) * CC + n];
            if (k0 + 9 < CC) w11 = W[(k0 + 9) * CC + n];
        }
        unsigned short h00 = f2bf(w00), h01 = f2bf(w01), h10 = f2bf(w10), h11 = f2bf(w11);
        unsigned short l00 = f2bf(w00 - bf2f(h00)), l01 = f2bf(w01 - bf2f(h01));
        unsigned short l10 = f2bf(w10 - bf2f(h10)), l11 = f2bf(w11 - bf2f(h11));
        uint4 v;
        v.x = (uint32_t)h00 | ((uint32_t)h01 << 16);
        v.y = (uint32_t)h10 | ((uint32_t)h11 << 16);
        v.z = (uint32_t)l00 | ((uint32_t)l01 << 16);
        v.w = (uint32_t)l10 | ((uint32_t)l11 << 16);
        g_Bpk[i] = v;
    }
}

// LN stats (warp per node) + fused edge in-degree count
__global__ void k_ln_stats(const float* __restrict__ x,
                           const int* __restrict__ batch,
                           const int* __restrict__ ei) {
    int gtid = blockIdx.x * blockDim.x + threadIdx.x;
    if (gtid < EE) atomicAdd(&g_cnt[ei[EE + gtid]], 1);

    int gw = gtid >> 5;
    int lane = threadIdx.x & 31;
    if (gw >= NN) return;
    const float* row = &x[(size_t)gw * CC];
    float s = 0.f, s2 = 0.f;
#pragma unroll
    for (int t = 0; t < 2; t++) {
        int c4 = lane + t * 32;
        if (c4 < CC / 4) {
            float4 v = *(const float4*)&row[c4 * 4];
            s += v.x + v.y + v.z + v.w;
            s2 += v.x * v.x + v.y * v.y + v.z * v.z + v.w * v.w;
        }
    }
    s = warpSum(s); s2 = warpSum(s2);
    if (lane == 0) {
        int b = batch[gw];
        atomicAdd(&g_gsum[b], s);
        atomicAdd(&g_gsq[b], s2);
        atomicAdd(&g_gcnt[b], 1.f);
    }
}

// A prep (warp per row): LN+ELU -> packed bf16 hi|lo u64
__global__ void k_aprep(const float* __restrict__ x, const int* __restrict__ batch,
                        const float* __restrict__ lnw, const float* __restrict__ lnb) {
    int gw = (blockIdx.x * blockDim.x + threadIdx.x) >> 5;
    int lane = threadIdx.x & 31;
    if (gw >= NN) return;
    float mean = 0.f, inv = 0.f;
    if (lane == 0) {
        int b = batch[gw];
        float denom = g_gcnt[b] * (float)CC;
        mean = g_gsum[b] / denom;
        float var = g_gsq[b] / denom - mean * mean;
        inv = rsqrtf(var + 1e-5f);
    }
    mean = __shfl_sync(0xffffffffu, mean, 0);
    inv = __shfl_sync(0xffffffffu, inv, 0);
    const float* xr = &x[(size_t)gw * CC];
#pragma unroll
    for (int t = 0; t < 4; t++) {
        int p = lane + t * 32;
        if (p >= KP) break;
        float v0 = 0.f, v1 = 0.f;
        int k = p * 2;
        if (k < CC) {
            float2 xv = *(const float2*)&xr[k];
            v0 = (xv.x - mean) * inv * __ldg(&lnw[k]) + __ldg(&lnb[k]);
            v1 = (xv.y - mean) * inv * __ldg(&lnw[k + 1]) + __ldg(&lnb[k + 1]);
            v0 = v0 > 0.f ? v0 : (__expf(v0) - 1.f);
            v1 = v1 > 0.f ? v1 : (__expf(v1) - 1.f);
        }
        unsigned short h0 = f2bf(v0), h1 = f2bf(v1);
        unsigned short l0 = f2bf(v0 - bf2f(h0)), l1 = f2bf(v1 - bf2f(h1));
        g_Apk[(size_t)gw * KP + p] =
            (unsigned long long)((uint32_t)h0 | ((uint32_t)h1 << 16)) |
            ((unsigned long long)((uint32_t)l0 | ((uint32_t)l1 << 16)) << 32);
    }
}

// ---- HMMA GEMM (round-14 best config): smem B halves, A prefetch, unrolled ----
__global__ void __launch_bounds__(256, 2) k_gemm_mma(const float* __restrict__ att_s,
                                                     const float* __restrict__ att_d) {
    extern __shared__ uint4 sB[];          // 5408 uint4 = 86.5 KB
    const int tid = threadIdx.x;
    const int half = blockIdx.x & 1;
    const int tile = (blockIdx.x >> 1) * 8 + (tid >> 5);
    const int lane = tid & 31;

    for (int i = tid; i < BHALF; i += 256)
        sB[i] = g_Bpk[half * BHALF + i];
    __syncthreads();

    if (tile >= ROWTILES) return;
    const int r = tile * 16 + (lane >> 2);
    const int q = lane & 3;

    float acc[13][4];
#pragma unroll
    for (int nt = 0; nt < 13; nt++)
#pragma unroll
        for (int t = 0; t < 4; t++) acc[nt][t] = 0.f;

    const unsigned long long* A0 = &g_Apk[(size_t)r * KP + q];
    const unsigned long long* A1 = &g_Apk[(size_t)(r + 8) * KP + q];
    unsigned long long v0 = A0[0], v1 = A1[0], v2 = A0[4], v3 = A1[4];

#pragma unroll
    for (int kt = 0; kt < KTILES; kt++) {
        uint32_t ahi[4] = {(uint32_t)v0, (uint32_t)v1, (uint32_t)v2, (uint32_t)v3};
        uint32_t alo[4] = {(uint32_t)(v0 >> 32), (uint32_t)(v1 >> 32),
                           (uint32_t)(v2 >> 32), (uint32_t)(v3 >> 32)};
        if (kt + 1 < KTILES) {
            int o = (kt + 1) * 8;
            v0 = A0[o]; v1 = A1[o]; v2 = A0[o + 4]; v3 = A1[o + 4];
        }
#pragma unroll
        for (int nt = 0; nt < 13; nt++) {
            uint4 b = sB[(nt * KTILES + kt) * 32 + lane];
            mma16816(acc[nt], ahi, b.x, b.y);
            mma16816(acc[nt], ahi, b.z, b.w);
            mma16816(acc[nt], alo, b.x, b.y);
        }
    }

    // epilogue: store xh + partial attention head dots (this half's columns)
    float s0A = 0.f, s1A = 0.f, s2A = 0.f, s3A = 0.f;
    float d0A = 0.f, d1A = 0.f, d2A = 0.f, d3A = 0.f;
    float s0B = 0.f, s1B = 0.f, s2B = 0.f, s3B = 0.f;
    float d0B = 0.f, d1B = 0.f, d2B = 0.f, d3B = 0.f;

#pragma unroll
    for (int nt = 0; nt < 13; nt++) {
        int n0 = (half * 13 + nt) * 8;
        if (n0 >= CC) break;
        int col = n0 + q * 2;
        *(float2*)&g_xh[(size_t)r * CC + col] = make_float2(acc[nt][0], acc[nt][1]);
        *(float2*)&g_xh[(size_t)(r + 8) * CC + col] = make_float2(acc[nt][2], acc[nt][3]);

        float2 as = __ldg((const float2*)&att_s[col]);
        float2 adv = __ldg((const float2*)&att_d[col]);
        float psA = acc[nt][0] * as.x + acc[nt][1] * as.y;
        float pdA = acc[nt][0] * adv.x + acc[nt][1] * adv.y;
        float psB = acc[nt][2] * as.x + acc[nt][3] * as.y;
        float pdB = acc[nt][2] * adv.x + acc[nt][3] * adv.y;
        int h = col / DD;   // pairs never straddle a head boundary (50 even)
        if (h == 0)      { s0A += psA; d0A += pdA; s0B += psB; d0B += pdB; }
        else if (h == 1) { s1A += psA; d1A += pdA; s1B += psB; d1B += pdB; }
        else if (h == 2) { s2A += psA; d2A += pdA; s2B += psB; d2B += pdB; }
        else             { s3A += psA; d3A += pdA; s3B += psB; d3B += pdB; }
    }
#pragma unroll
    for (int o = 1; o <= 2; o <<= 1) {
        s0A += __shfl_xor_sync(0xffffffffu, s0A, o);
        s1A += __shfl_xor_sync(0xffffffffu, s1A, o);
        s2A += __shfl_xor_sync(0xffffffffu, s2A, o);
        s3A += __shfl_xor_sync(0xffffffffu, s3A, o);
        d0A += __shfl_xor_sync(0xffffffffu, d0A, o);
        d1A += __shfl_xor_sync(0xffffffffu, d1A, o);
        d2A += __shfl_xor_sync(0xffffffffu, d2A, o);
        d3A += __shfl_xor_sync(0xffffffffu, d3A, o);
        s0B += __shfl_xor_sync(0xffffffffu, s0B, o);
        s1B += __shfl_xor_sync(0xffffffffu, s1B, o);
        s2B += __shfl_xor_sync(0xffffffffu, s2B, o);
        s3B += __shfl_xor_sync(0xffffffffu, s3B, o);
        d0B += __shfl_xor_sync(0xffffffffu, d0B, o);
        d1B += __shfl_xor_sync(0xffffffffu, d1B, o);
        d2B += __shfl_xor_sync(0xffffffffu, d2B, o);
        d3B += __shfl_xor_sync(0xffffffffu, d3B, o);
    }
    if (q == 0) {
        red_add_v4(&g_asrc[r * 4], s0A, s1A, s2A, s3A);
        red_add_v4(&g_adst[r * 4], d0A, d1A, d2A, d3A);
        red_add_v4(&g_asrc[(r + 8) * 4], s0B, s1B, s2B, s3B);
        red_add_v4(&g_adst[(r + 8) * 4], d0B, d1B, d2B, d3B);
    }
}

// ---- CSR build ----
__global__ void k_scan_block() {
    __shared__ int sm[SCAN_B];
    int i = blockIdx.x * SCAN_B + threadIdx.x;
    int v = (i < NN) ? g_cnt[i] : 0;
    sm[threadIdx.x] = v;
    __syncthreads();
    for (int o = 1; o < SCAN_B; o <<= 1) {
        int t = (threadIdx.x >= o) ? sm[threadIdx.x - o] : 0;
        __syncthreads();
        sm[threadIdx.x] += t;
        __syncthreads();
    }
    if (i < NN) g_base[i] = sm[threadIdx.x] - v;
    if (threadIdx.x == SCAN_B - 1) g_bsum[blockIdx.x] = sm[threadIdx.x];
}

__global__ void k_scan_add() {
    __shared__ float s_off;
    if (threadIdx.x < 32) {
        int bid = blockIdx.x;
        int off = 0;
        for (int j = (int)threadIdx.x; j < bid; j += 32) off += g_bsum[j];
#pragma unroll
        for (int o = 16; o; o >>= 1) off += __shfl_xor_sync(0xffffffffu, off, o);
        if (threadIdx.x == 0) s_off = __int_as_float(off);
    }
    __syncthreads();
    int off = __float_as_int(s_off);
    int i = blockIdx.x * SCAN_B + threadIdx.x;
    if (i >= NN) return;
    int v = g_base[i] + off;
    g_base[i] = v;
    g_cursor[i] = v;
}

__global__ void k_fill(const int* __restrict__ ei) {
    int i = blockIdx.x * blockDim.x + threadIdx.x;
    if (i >= EE) return;
    int dst = ei[EE + i];
    int pos = atomicAdd(&g_cursor[dst], 1);
    g_csrc[pos] = ei[i];
}

// ---- GAT softmax + aggregation + SAG score projections ----
// deg<=32 fast path: single gather (alphas staged in smem through the max)
__global__ void __launch_bounds__(256) k_gat(float* __restrict__ out,
                                             const float* __restrict__ bias,
                                             const float* __restrict__ w_rel,
                                             const float* __restrict__ w_root,
                                             const float* __restrict__ b_rel) {
    __shared__ float s_e[8][32][4];
    __shared__ int s_src[8][32];
    __shared__ float s_zz[8][4], s_ee[8][4];
    int w = threadIdx.x >> 5;
    int lane = threadIdx.x & 31;
    int n = blockIdx.x * 8 + w;
    if (n >= NN) return;
    int base = g_base[n];
    int deg = g_cnt[n];
    const bool two = lane < 18;

    const int c0 = lane * 4;
    const int c1 = (lane + 32) * 4;
    const int h00 = c0 / DD, h01 = (c0 + 1) / DD, h02 = (c0 + 2) / DD, h03 = (c0 + 3) / DD;
    const int h10 = two ? c1 / DD : 3, h11 = two ? (c1 + 1) / DD : 3;
    const int h12 = two ? (c1 + 2) / DD : 3, h13 = two ? (c1 + 3) / DD : 3;

    float4 ad = *(const float4*)&g_adst[n * 4];
    float4 asn = *(const float4*)&g_asrc[n * 4];
    float sf0 = lrelu(asn.x + ad.x), sf1 = lrelu(asn.y + ad.y);
    float sf2 = lrelu(asn.z + ad.z), sf3 = lrelu(asn.w + ad.w);

    float4 acc0 = make_float4(0.f, 0.f, 0.f, 0.f);
    float4 acc1 = make_float4(0.f, 0.f, 0.f, 0.f);
    float z0 = 0.f, z1 = 0.f, z2 = 0.f, z3 = 0.f;
    float m0, m1, m2, m3;

    if (deg <= 32) {
        // ---- single-gather fast path ----
        float a0 = -FLT_MAX, a1 = -FLT_MAX, a2 = -FLT_MAX, a3 = -FLT_MAX;
        if (lane < deg) {
            int src = g_csrc[base + lane];
            s_src[w][lane] = src;
            float4 as = *(const float4*)&g_asrc[src * 4];
            a0 = lrelu(as.x + ad.x); a1 = lrelu(as.y + ad.y);
            a2 = lrelu(as.z + ad.z); a3 = lrelu(as.w + ad.w);
        }
        m0 = warpMax(fmaxf(a0, sf0)); m1 = warpMax(fmaxf(a1, sf1));
        m2 = warpMax(fmaxf(a2, sf2)); m3 = warpMax(fmaxf(a3, sf3));
        if (lane < deg) {
            float e0 = __expf(a0 - m0), e1 = __expf(a1 - m1);
            float e2 = __expf(a2 - m2), e3 = __expf(a3 - m3);
            s_e[w][lane][0] = e0; s_e[w][lane][1] = e1;
            s_e[w][lane][2] = e2; s_e[w][lane][3] = e3;
            z0 = e0; z1 = e1; z2 = e2; z3 = e3;
        }
        __syncwarp();
        for (int jj = 0; jj < deg; jj++) {
            int src = s_src[w][jj];
            const float4* xr = (const float4*)&g_xh[(size_t)src * CC];
            float4 xv0 = xr[lane];
            acc0.x += xv0.x * s_e[w][jj][h00];
            acc0.y += xv0.y * s_e[w][jj][h01];
            acc0.z += xv0.z * s_e[w][jj][h02];
            acc0.w += xv0.w * s_e[w][jj][h03];
            if (two) {
                float4 xv1 = xr[lane + 32];
                acc1.x += xv1.x * s_e[w][jj][h10];
                acc1.y += xv1.y * s_e[w][jj][h11];
                acc1.z += xv1.z * s_e[w][jj][h12];
                acc1.w += xv1.w * s_e[w][jj][h13];
            }
        }
        __syncwarp();
    } else {
        // ---- general chunked two-pass path ----
        m0 = sf0; m1 = sf1; m2 = sf2; m3 = sf3;
        for (int j = lane; j < deg; j += 32) {
            int src = g_csrc[base + j];
            float4 as = *(const float4*)&g_asrc[src * 4];
            m0 = fmaxf(m0, lrelu(as.x + ad.x));
            m1 = fmaxf(m1, lrelu(as.y + ad.y));
            m2 = fmaxf(m2, lrelu(as.z + ad.z));
            m3 = fmaxf(m3, lrelu(as.w + ad.w));
        }
        m0 = warpMax(m0); m1 = warpMax(m1); m2 = warpMax(m2); m3 = warpMax(m3);

        for (int cbase = 0; cbase < deg; cbase += 32) {
            int j = cbase + lane;
            int cn = min(32, deg - cbase);
            if (j < deg) {
                int src = g_csrc[base + j];
                s_src[w][lane] = src;
                float4 as = *(const float4*)&g_asrc[src * 4];
                float e0 = __expf(lrelu(as.x + ad.x) - m0);
                float e1 = __expf(lrelu(as.y + ad.y) - m1);
                float e2 = __expf(lrelu(as.z + ad.z) - m2);
                float e3 = __expf(lrelu(as.w + ad.w) - m3);
                s_e[w][lane][0] = e0; s_e[w][lane][1] = e1;
                s_e[w][lane][2] = e2; s_e[w][lane][3] = e3;
                z0 += e0; z1 += e1; z2 += e2; z3 += e3;
            }
            __syncwarp();
            for (int jj = 0; jj < cn; jj++) {
                int src = s_src[w][jj];
                const float4* xr = (const float4*)&g_xh[(size_t)src * CC];
                float4 xv0 = xr[lane];
                acc0.x += xv0.x * s_e[w][jj][h00];
                acc0.y += xv0.y * s_e[w][jj][h01];
                acc0.z += xv0.z * s_e[w][jj][h02];
                acc0.w += xv0.w * s_e[w][jj][h03];
                if (two) {
                    float4 xv1 = xr[lane + 32];
                    acc1.x += xv1.x * s_e[w][jj][h10];
                    acc1.y += xv1.y * s_e[w][jj][h11];
                    acc1.z += xv1.z * s_e[w][jj][h12];
                    acc1.w += xv1.w * s_e[w][jj][h13];
                }
            }
            __syncwarp();
        }
    }
    z0 = warpSum(z0); z1 = warpSum(z1); z2 = warpSum(z2); z3 = warpSum(z3);

    float es0 = __expf(sf0 - m0), es1 = __expf(sf1 - m1);
    float es2 = __expf(sf2 - m2), es3 = __expf(sf3 - m3);
    z0 += es0 + 1e-16f; z1 += es1 + 1e-16f;
    z2 += es2 + 1e-16f; z3 += es3 + 1e-16f;
    if (lane == 0) {
        s_zz[w][0] = z0; s_zz[w][1] = z1; s_zz[w][2] = z2; s_zz[w][3] = z3;
        s_ee[w][0] = es0; s_ee[w][1] = es1; s_ee[w][2] = es2; s_ee[w][3] = es3;
    }
    __syncwarp();

    const float4* xn4 = (const float4*)&g_xh[(size_t)n * CC];
    float4* orow4 = (float4*)&out[(size_t)n * CC];
    float sr = 0.f, sb = 0.f;
    {
        float4 xv = xn4[lane];
        float4 bv = __ldg((const float4*)&bias[c0]);
        float4 wr = __ldg((const float4*)&w_rel[c0]);
        float4 wo = __ldg((const float4*)&w_root[c0]);
        float4 v;
        v.x = (acc0.x + xv.x * s_ee[w][h00]) / s_zz[w][h00] + bv.x;
        v.y = (acc0.y + xv.y * s_ee[w][h01]) / s_zz[w][h01] + bv.y;
        v.z = (acc0.z + xv.z * s_ee[w][h02]) / s_zz[w][h02] + bv.z;
        v.w = (acc0.w + xv.w * s_ee[w][h03]) / s_zz[w][h03] + bv.w;
        orow4[lane] = v;
        sr += v.x * wr.x + v.y * wr.y + v.z * wr.z + v.w * wr.w;
        sb += v.x * wo.x + v.y * wo.y + v.z * wo.z + v.w * wo.w;
    }
    if (two) {
        float4 xv = xn4[lane + 32];
        float4 bv = __ldg((const float4*)&bias[c1]);
        float4 wr = __ldg((const float4*)&w_rel[c1]);
        float4 wo = __ldg((const float4*)&w_root[c1]);
        float4 v;
        v.x = (acc1.x + xv.x * s_ee[w][h10]) / s_zz[w][h10] + bv.x;
        v.y = (acc1.y + xv.y * s_ee[w][h11]) / s_zz[w][h11] + bv.y;
        v.z = (acc1.z + xv.z * s_ee[w][h12]) / s_zz[w][h12] + bv.z;
        v.w = (acc1.w + xv.w * s_ee[w][h13]) / s_zz[w][h13] + bv.w;
        orow4[lane + 32] = v;
        sr += v.x * wr.x + v.y * wr.y + v.z * wr.z + v.w * wr.w;
        sb += v.x * wo.x + v.y * wo.y + v.z * wo.z + v.w * wo.w;
    }
    sr = warpSum(sr); sb = warpSum(sb);
    if (lane == 0) {
        g_srel[n] = sr;
        g_sbase[n] = sb + __ldg(&b_rel[0]);
    }
}

__global__ void k_score_agg(const int* __restrict__ batch) {
    int i = blockIdx.x * blockDim.x + threadIdx.x;
    if (i >= NN) return;
    int base = g_base[i], deg = g_cnt[i];
    float s = 0.f;
#pragma unroll 4
    for (int j = 0; j < deg; j++) s += g_srel[g_csrc[base + j]];
    s += g_sbase[i];
    g_sbase[i] = s;
    atomicMax(&g_gmu[batch[i]], fkey(s));
}

__global__ void k_score_exp(const int* __restrict__ batch) {
    int i = blockIdx.x * blockDim.x + threadIdx.x;
    if (i >= NN) return;
    int b = batch[i];
    float es = expf(g_sbase[i] - funkey(g_gmu[b]));
    g_es[i] = es;
    atomicAdd(&g_gz[b], es);
}

// finalize: warp per 16-node run; inline scale; per-graph register accumulation
__global__ void k_finalize(float* __restrict__ out, float* __restrict__ outg,
                           const int* __restrict__ batch) {
    int gw = (blockIdx.x * blockDim.x + threadIdx.x) >> 5;
    int lane = threadIdx.x & 31;
    if (gw >= NN / 16) return;
    const bool two = lane < 18;
    int n0 = gw * 16;
    float4 a0 = make_float4(0.f, 0.f, 0.f, 0.f);
    float4 a1 = make_float4(0.f, 0.f, 0.f, 0.f);
    int curb = batch[n0];
    for (int j = 0; j < 16; j++) {
        int n = n0 + j;
        int b = batch[n];
        if (b != curb) {
            red_add_v4(&outg[(size_t)curb * CC + lane * 4], a0.x, a0.y, a0.z, a0.w);
            if (two)
                red_add_v4(&outg[(size_t)curb * CC + (lane + 32) * 4], a1.x, a1.y, a1.z, a1.w);
            a0 = make_float4(0.f, 0.f, 0.f, 0.f);
            a1 = make_float4(0.f, 0.f, 0.f, 0.f);
            curb = b;
        }
        float sc = g_es[n] / g_gz[b];
        float4* orow = (float4*)&out[(size_t)n * CC];
        float4 v = orow[lane];
        v.x *= sc; v.y *= sc; v.z *= sc; v.w *= sc;
        orow[lane] = v;
        a0.x += v.x; a0.y += v.y; a0.z += v.z; a0.w += v.w;
        if (two) {
            float4 v1 = orow[lane + 32];
            v1.x *= sc; v1.y *= sc; v1.z *= sc; v1.w *= sc;
            orow[lane + 32] = v1;
            a1.x += v1.x; a1.y += v1.y; a1.z += v1.z; a1.w += v1.w;
        }
    }
    red_add_v4(&outg[(size_t)curb * CC + lane * 4], a0.x, a0.y, a0.z, a0.w);
    if (two)
        red_add_v4(&outg[(size_t)curb * CC + (lane + 32) * 4], a1.x, a1.y, a1.z, a1.w);
}

// ---------------- launch ----------------------------------------------------
extern "C" void kernel_launch(void* const* d_in, const int* in_sizes, int n_in,
                              void* d_out, int out_size) {
    const float* x = (const float*)d_in[0];
    const int* ei = (const int*)d_in[1];
    const int* batch = (const int*)d_in[2];
    const float* ln_w = (const float*)d_in[3];
    const float* ln_b = (const float*)d_in[4];
    const float* W_gat = (const float*)d_in[5];
    const float* att_s = (const float*)d_in[6];
    const float* att_d = (const float*)d_in[7];
    const float* bias = (const float*)d_in[8];
    const float* w_rel = (const float*)d_in[9];
    const float* b_rel = (const float*)d_in[10];
    const float* w_root = (const float*)d_in[11];

    float* out = (float*)d_out;
    float* outg = out + (size_t)NN * CC;

    const int T = 256;
    const int warpNodeBlocks = (NN + 7) / 8;
    const int nodeBlocks = (NN + T - 1) / T;
    const int edgeBlocks = (EE + T - 1) / T;
    (void)in_sizes; (void)n_in; (void)out_size;

    cudaFuncSetAttribute(k_gemm_mma, cudaFuncAttributeMaxDynamicSharedMemorySize,
                         SMEM_B);

    k_init<<<nodeBlocks, T>>>(outg, W_gat);
    k_ln_stats<<<warpNodeBlocks, T>>>(x, batch, ei);   // + edge count
    k_aprep<<<warpNodeBlocks, T>>>(x, batch, ln_w, ln_b);

    // 4th launch -> profiled
    k_gemm_mma<<<((ROWTILES + 7) / 8) * 2, 256, SMEM_B>>>(att_s, att_d);

    k_scan_block<<<SCAN_NB, SCAN_B>>>();
    k_scan_add<<<SCAN_NB, SCAN_B>>>();
    k_fill<<<edgeBlocks, T>>>(ei);

    k_gat<<<warpNodeBlocks, T>>>(out, bias, w_rel, w_root, b_rel);

    k_score_agg<<<nodeBlocks, T>>>(batch);
    k_score_exp<<<nodeBlocks, T>>>(batch);
    k_finalize<<<(NN / 16 + 7) / 8, T>>>(out, outg, batch);
}